// round 2
// baseline (speedup 1.0000x reference)
#include <cuda_runtime.h>
#include <cstdint>

#define NN 50000
#define RR 16
#define DD 200
#define EE 400000

#define BM 128
#define TK 8
#define NT 320   // 32 rowgrps x 10 colgrps

// ---------------- scratch (device globals; no runtime allocation) ----------
__device__ float g_sums[(size_t)RR * NN * DD];  // 640 MB: per-(r,dst) feature sums
__device__ int   g_cnt[RR * NN];                // per-(r,dst) edge counts
__device__ int   g_list[RR * NN];               // per-relation active dst list
__device__ int   g_listcnt[RR];                 // active count per relation
__device__ float g_h[NN * DD];                  // layer-1 activations

// vectorized global reduction (PTX 8.1+, sm_90+): 16B-aligned address required
__device__ __forceinline__ void red4(float* p, float4 v) {
    asm volatile("red.global.add.v4.f32 [%0], {%1,%2,%3,%4};"
                 :: "l"(p), "f"(v.x), "f"(v.y), "f"(v.z), "f"(v.w)
                 : "memory");
}

// ---------------- kernels --------------------------------------------------

__global__ void k_zero() {
    size_t tid = (size_t)blockIdx.x * blockDim.x + threadIdx.x;
    size_t stride = (size_t)gridDim.x * blockDim.x;
    float4* s4 = (float4*)g_sums;
    const size_t n4 = (size_t)RR * NN * DD / 4;
    float4 z = make_float4(0.f, 0.f, 0.f, 0.f);
    for (size_t i = tid; i < n4; i += stride) s4[i] = z;
    for (size_t i = tid; i < (size_t)RR * NN; i += stride) g_cnt[i] = 0;
    if (tid < RR) g_listcnt[tid] = 0;
}

// one warp per edge: scatter x[src] into g_sums[etype*N+dst], count edges
__global__ void k_scatter(const float* __restrict__ x,
                          const int* __restrict__ src,
                          const int* __restrict__ dst,
                          const int* __restrict__ et) {
    int w = (blockIdx.x * blockDim.x + threadIdx.x) >> 5;
    int lane = threadIdx.x & 31;
    if (w >= EE) return;
    int s = src[w], d = dst[w], t = et[w];
    size_t seg = (size_t)t * NN + d;
    const float4* xr = (const float4*)(x + (size_t)s * DD);
    float* outp = g_sums + seg * DD;
    #pragma unroll 2
    for (int i = lane; i < DD / 4; i += 32) {
        float4 v = xr[i];
        red4(outp + i * 4, v);
    }
    if (lane == 0) atomicAdd(&g_cnt[seg], 1);
}

__global__ void k_compact() {
    int i = blockIdx.x * blockDim.x + threadIdx.x;
    if (i >= RR * NN) return;
    if (g_cnt[i] > 0) {
        int r = i / NN, n = i - r * NN;
        int p = atomicAdd(&g_listcnt[r], 1);
        g_list[r * NN + p] = n;
    }
}

__global__ void k_relu() {
    float4* h4 = (float4*)g_h;
    const int n4 = NN * DD / 4;
    for (int i = blockIdx.x * blockDim.x + threadIdx.x; i < n4;
         i += gridDim.x * blockDim.x) {
        float4 v = h4[i];
        v.x = fmaxf(v.x, 0.f); v.y = fmaxf(v.y, 0.f);
        v.z = fmaxf(v.z, 0.f); v.w = fmaxf(v.w, 0.f);
        h4[i] = v;
    }
}

// Tiled GEMM. REL=false: out[n,:] = A[n,:] @ W + bias  (dense, plain store)
//             REL=true : out[n,:] += (sums[r,n,:]/cnt) @ W[r]  (indirect rows,
//                        vectorized atomic accumulate)
template <bool REL>
__global__ __launch_bounds__(NT, 1)
void k_gemm(const float* __restrict__ A,
            const float* __restrict__ W,
            const float* __restrict__ bias,
            float* __restrict__ out) {
    __shared__ float As[TK][BM];
    __shared__ float Bs[TK][DD];
    __shared__ int   srow[BM];
    __shared__ float sscale[BM];

    const int r  = REL ? blockIdx.y : 0;
    const int m0 = blockIdx.x * BM;

    int valid;
    if (REL) {
        valid = g_listcnt[r] - m0;
        if (valid <= 0) return;
        if (valid > BM) valid = BM;
    } else {
        valid = NN - m0;
        if (valid > BM) valid = BM;
    }

    const int tid = threadIdx.x;

    if (tid < BM) {
        if (tid < valid) {
            if (REL) {
                int n = g_list[r * NN + m0 + tid];
                srow[tid] = n;
                sscale[tid] = 1.0f / (float)g_cnt[r * NN + n];
            } else {
                srow[tid] = m0 + tid;
                sscale[tid] = 1.0f;
            }
        } else {
            srow[tid] = -1;
            sscale[tid] = 0.f;
        }
    }
    __syncthreads();

    const float* Wr = REL ? (W + (size_t)r * DD * DD) : W;

    float acc[4][20];
    #pragma unroll
    for (int i = 0; i < 4; i++)
        #pragma unroll
        for (int j = 0; j < 20; j++) acc[i][j] = 0.f;

    const int rowgrp = tid / 10;          // 0..31
    const int colgrp = tid - rowgrp * 10; // 0..9
    const int c0 = colgrp * 20;

    for (int k0 = 0; k0 < DD; k0 += TK) {
        // --- load A tile (scaled, row-indirect) ---
        if (tid < 256) {
            int row = tid >> 1, part = tid & 1;
            float4 v = make_float4(0.f, 0.f, 0.f, 0.f);
            int n = srow[row];
            if (n >= 0) {
                const float* ap = REL
                    ? (g_sums + ((size_t)r * NN + n) * DD)
                    : (A + (size_t)n * DD);
                v = *(const float4*)(ap + k0 + part * 4);
                float s = sscale[row];
                v.x *= s; v.y *= s; v.z *= s; v.w *= s;
            }
            int kb = part * 4;
            As[kb + 0][row] = v.x; As[kb + 1][row] = v.y;
            As[kb + 2][row] = v.z; As[kb + 3][row] = v.w;
        }
        // --- load B tile (TK x 200, contiguous) ---
        {
            const float4* w4 = (const float4*)(Wr + (size_t)k0 * DD);
            float4* b4 = (float4*)&Bs[0][0];
            #pragma unroll 2
            for (int idx = tid; idx < TK * DD / 4; idx += NT)
                b4[idx] = w4[idx];
        }
        __syncthreads();

        #pragma unroll
        for (int kk = 0; kk < TK; kk++) {
            float4 a = *(const float4*)&As[kk][rowgrp * 4];
            float av[4] = {a.x, a.y, a.z, a.w};
            float bv[20];
            #pragma unroll
            for (int j = 0; j < 5; j++) {
                float4 t4 = *(const float4*)&Bs[kk][c0 + j * 4];
                bv[j * 4 + 0] = t4.x; bv[j * 4 + 1] = t4.y;
                bv[j * 4 + 2] = t4.z; bv[j * 4 + 3] = t4.w;
            }
            #pragma unroll
            for (int i = 0; i < 4; i++)
                #pragma unroll
                for (int j = 0; j < 20; j++)
                    acc[i][j] = fmaf(av[i], bv[j], acc[i][j]);
        }
        __syncthreads();
    }

    // --- epilogue ---
    #pragma unroll
    for (int i = 0; i < 4; i++) {
        int row = rowgrp * 4 + i;
        if (row >= valid) continue;
        int n = srow[row];
        float* op = out + (size_t)n * DD + c0;
        if (REL) {
            #pragma unroll
            for (int j = 0; j < 5; j++) {
                float4 v = make_float4(acc[i][j*4+0], acc[i][j*4+1],
                                       acc[i][j*4+2], acc[i][j*4+3]);
                red4(op + j * 4, v);
            }
        } else {
            #pragma unroll
            for (int j = 0; j < 5; j++) {
                float4 v;
                v.x = acc[i][j*4+0] + bias[c0 + j*4 + 0];
                v.y = acc[i][j*4+1] + bias[c0 + j*4 + 1];
                v.z = acc[i][j*4+2] + bias[c0 + j*4 + 2];
                v.w = acc[i][j*4+3] + bias[c0 + j*4 + 3];
                *(float4*)(op + j * 4) = v;
            }
        }
    }
}

// ---------------- launch ----------------------------------------------------

extern "C" void kernel_launch(void* const* d_in, const int* in_sizes, int n_in,
                              void* d_out, int out_size) {
    const int*   ei    = (const int*)d_in[0];      // [2, E]
    const int*   et    = (const int*)d_in[1];      // [E]
    const float* emb   = (const float*)d_in[2];    // [N, D]
    const float* W1    = (const float*)d_in[3];    // [R, D, D]
    const float* root1 = (const float*)d_in[4];    // [D, D]
    const float* b1    = (const float*)d_in[5];    // [D]
    const float* W2    = (const float*)d_in[6];
    const float* root2 = (const float*)d_in[7];
    const float* b2    = (const float*)d_in[8];
    float* out = (float*)d_out;

    const int* src = ei;
    const int* dst = ei + EE;

    float* hptr = nullptr;
    cudaGetSymbolAddress((void**)&hptr, g_h);

    const int gemm_mblocks = (NN + BM - 1) / BM;   // 391
    const int scatter_blocks = EE / 8;             // 8 warps/block
    const int compact_blocks = (RR * NN + 255) / 256;

    // ---- layer 1 ----
    k_zero<<<4096, 256>>>();
    k_scatter<<<scatter_blocks, 256>>>(emb, src, dst, et);
    k_compact<<<compact_blocks, 256>>>();
    k_gemm<false><<<dim3(gemm_mblocks, 1), NT>>>(emb, root1, b1, hptr);
    k_gemm<true ><<<dim3(gemm_mblocks, RR), NT>>>(nullptr, W1, nullptr, hptr);
    k_relu<<<2048, 256>>>();

    // ---- layer 2 ----
    k_zero<<<4096, 256>>>();
    k_scatter<<<scatter_blocks, 256>>>(hptr, src, dst, et);
    k_compact<<<compact_blocks, 256>>>();
    k_gemm<false><<<dim3(gemm_mblocks, 1), NT>>>(hptr, root2, b2, out);
    k_gemm<true ><<<dim3(gemm_mblocks, RR), NT>>>(nullptr, W2, nullptr, out);
}